// round 2
// baseline (speedup 1.0000x reference)
#include <cuda_runtime.h>
#include <cuda_bf16.h>
#include <math.h>

// ================= problem constants =================
#define LSEQ 4096
#define EMB 2048
#define KVHEADS 4
#define NSLOTS 32
#define NDIMS 1024          // 512 key dims + 512 value dims
#define NCHUNK 32
#define CLEN 128            // LSEQ / NCHUNK
#define RHALF 0.70710678118654752f
#define INV_SCALE 0.29730177875068026f   // 1 / 128^0.25
#define EPSF 1e-6f

// ================= device scratch (static, allocation-free) =================
__device__ float d_kk[LSEQ * 512];                     // (k@wk)/scale
__device__ float d_vv[LSEQ * 512];                     // v@wv
__device__ float d_qq[LSEQ * 2048];                    // (q@wq)/scale + query_pos
__device__ float d_attn[LSEQ * 2048];                  // attention output pre-wd
__device__ float d_state[(size_t)LSEQ * NDIMS * NSLOTS];  // full scan states (536MB)
__device__ float d_lend[NCHUNK * NDIMS * NSLOTS];      // local chunk-end states
__device__ float d_carryb[NCHUNK * NDIMS * NSLOTS];    // carry INTO each chunk
__device__ float d_amat[NCHUNK * NSLOTS * NSLOTS];     // composed chunk gate maps

// ================= gate recurrence step =================
template <int KEY>
__device__ __forceinline__ void merge_shift(float (&s)[NSLOTS]) {
  s[KEY] = RHALF * (s[KEY] + s[KEY - 1]);
#pragma unroll
  for (int j = KEY - 1; j >= 1; --j) s[j] = s[j - 1];
}

__device__ __forceinline__ void gate_step(float (&s)[NSLOTS], int kdiv) {
  switch (kdiv) {
    case 1: merge_shift<4>(s); break;
    case 2: merge_shift<8>(s); break;
    case 3: merge_shift<12>(s); break;
    case 4: merge_shift<16>(s); break;
    case 5: merge_shift<20>(s); break;
    case 6: merge_shift<24>(s); break;
    case 7: merge_shift<28>(s); break;
    default:
#pragma unroll
      for (int j = 31; j >= 1; --j) s[j] = s[j - 1];
      break;
  }
}

__device__ __forceinline__ int key_div4(int t) {
  return __ffs(~(t & 1023));
}

// ================= bf16 split helpers =================
__device__ __forceinline__ void split_bf16(float x, __nv_bfloat16& h, __nv_bfloat16& l) {
  h = __float2bfloat16_rn(x);
  l = __float2bfloat16_rn(x - __bfloat162float(h));
}

// ================= tensor-core GEMM with 3-term bf16 error compensation ==========
// C[M,N] = alpha * A[M,K] @ B[K,N] (+ bias[n&127]).
// A = Ah + Al, B = Bh + Bl (bf16 splits); D = Ah*Bh + Al*Bh + Ah*Bl.
// CTA tile 128x128x32, 256 threads, 8 warps as 2(M) x 4(N) -> warp tile 64x32.
#define TBM 128
#define TBN 128
#define TBK 32
#define APAD 40   // bf16 elements per smem row (conflict-free fragment loads)

__device__ __forceinline__ void mma16816(float (&c)[4], const unsigned (&a)[4],
                                         unsigned b0, unsigned b1) {
  asm volatile(
      "mma.sync.aligned.m16n8k16.row.col.f32.bf16.bf16.f32 "
      "{%0,%1,%2,%3}, {%4,%5,%6,%7}, {%8,%9}, {%0,%1,%2,%3};"
      : "+f"(c[0]), "+f"(c[1]), "+f"(c[2]), "+f"(c[3])
      : "r"(a[0]), "r"(a[1]), "r"(a[2]), "r"(a[3]), "r"(b0), "r"(b1));
}

__global__ __launch_bounds__(256) void mma_gemm(
    const float* __restrict__ A, const float* __restrict__ B, float* __restrict__ C,
    int M, int N, int K, float alpha, const float* __restrict__ bias) {
  __shared__ __nv_bfloat16 Ah[TBM][APAD];
  __shared__ __nv_bfloat16 Al[TBM][APAD];
  __shared__ __nv_bfloat16 Bh[TBN][APAD];   // stored n-major: Bh[n][k]
  __shared__ __nv_bfloat16 Bl[TBN][APAD];

  const int tid = threadIdx.x;
  const int lane = tid & 31;
  const int warp = tid >> 5;
  const int wm = (warp & 1) * 64;    // warp M offset within CTA tile
  const int wn = (warp >> 1) * 32;   // warp N offset
  const int g = lane >> 2;           // group (row/col within fragment)
  const int t = lane & 3;            // thread-in-group

  const int crow = blockIdx.y * TBM;
  const int ccol = blockIdx.x * TBN;

  float acc[4][4][4];
#pragma unroll
  for (int i = 0; i < 4; i++)
#pragma unroll
    for (int j = 0; j < 4; j++)
#pragma unroll
      for (int r = 0; r < 4; r++) acc[i][j][r] = 0.f;

  for (int bk = 0; bk < K; bk += TBK) {
    // ---- load A tile 128x32 fp32, split into hi/lo bf16 ----
#pragma unroll
    for (int i = 0; i < 4; i++) {
      int idx = tid + i * 256;
      int r = idx >> 3;
      int c = (idx & 7) * 4;
      float4 av = *(const float4*)(A + (size_t)(crow + r) * K + bk + c);
      __nv_bfloat16 h0, l0, h1, l1, h2, l2, h3, l3;
      split_bf16(av.x, h0, l0);
      split_bf16(av.y, h1, l1);
      split_bf16(av.z, h2, l2);
      split_bf16(av.w, h3, l3);
      *(__nv_bfloat162*)&Ah[r][c]     = __nv_bfloat162(h0, h1);
      *(__nv_bfloat162*)&Ah[r][c + 2] = __nv_bfloat162(h2, h3);
      *(__nv_bfloat162*)&Al[r][c]     = __nv_bfloat162(l0, l1);
      *(__nv_bfloat162*)&Al[r][c + 2] = __nv_bfloat162(l2, l3);
    }
    // ---- load B tile 32x128 fp32, split + transpose into Bs[n][k] ----
#pragma unroll
    for (int i = 0; i < 4; i++) {
      int idx = tid + i * 256;
      int kr = idx >> 5;
      int c = (idx & 31) * 4;
      float4 bv = *(const float4*)(B + (size_t)(bk + kr) * N + ccol + c);
      __nv_bfloat16 h, l;
      split_bf16(bv.x, h, l); Bh[c + 0][kr] = h; Bl[c + 0][kr] = l;
      split_bf16(bv.y, h, l); Bh[c + 1][kr] = h; Bl[c + 1][kr] = l;
      split_bf16(bv.z, h, l); Bh[c + 2][kr] = h; Bl[c + 2][kr] = l;
      split_bf16(bv.w, h, l); Bh[c + 3][kr] = h; Bl[c + 3][kr] = l;
    }
    __syncthreads();

#pragma unroll
    for (int ks = 0; ks < 2; ks++) {
      const int k0 = ks * 16;
      unsigned ah[4][4], al[4][4];
#pragma unroll
      for (int i = 0; i < 4; i++) {
        int r = wm + i * 16 + g;
        ah[i][0] = *(const unsigned*)&Ah[r][k0 + 2 * t];
        ah[i][1] = *(const unsigned*)&Ah[r + 8][k0 + 2 * t];
        ah[i][2] = *(const unsigned*)&Ah[r][k0 + 2 * t + 8];
        ah[i][3] = *(const unsigned*)&Ah[r + 8][k0 + 2 * t + 8];
        al[i][0] = *(const unsigned*)&Al[r][k0 + 2 * t];
        al[i][1] = *(const unsigned*)&Al[r + 8][k0 + 2 * t];
        al[i][2] = *(const unsigned*)&Al[r][k0 + 2 * t + 8];
        al[i][3] = *(const unsigned*)&Al[r + 8][k0 + 2 * t + 8];
      }
#pragma unroll
      for (int j = 0; j < 4; j++) {
        int n = wn + j * 8 + g;
        unsigned bh0 = *(const unsigned*)&Bh[n][k0 + 2 * t];
        unsigned bh1 = *(const unsigned*)&Bh[n][k0 + 2 * t + 8];
        unsigned bl0 = *(const unsigned*)&Bl[n][k0 + 2 * t];
        unsigned bl1 = *(const unsigned*)&Bl[n][k0 + 2 * t + 8];
#pragma unroll
        for (int i = 0; i < 4; i++) {
          mma16816(acc[i][j], ah[i], bh0, bh1);
          mma16816(acc[i][j], al[i], bh0, bh1);
          mma16816(acc[i][j], ah[i], bl0, bl1);
        }
      }
    }
    __syncthreads();
  }

  // ---- epilogue ----
#pragma unroll
  for (int i = 0; i < 4; i++) {
#pragma unroll
    for (int j = 0; j < 4; j++) {
      int row = crow + wm + i * 16 + g;
      int col = ccol + wn + j * 8 + 2 * t;
      float b0 = bias ? bias[col & 127] : 0.f;
      float b1 = bias ? bias[(col + 1) & 127] : 0.f;
      float2 v0 = make_float2(alpha * acc[i][j][0] + b0, alpha * acc[i][j][1] + b1);
      float2 v1 = make_float2(alpha * acc[i][j][2] + b0, alpha * acc[i][j][3] + b1);
      *(float2*)(C + (size_t)row * N + col) = v0;
      *(float2*)(C + (size_t)(row + 8) * N + col) = v1;
    }
  }
}

// ================= scan pass A: composed chunk maps =================
__global__ void amat_kernel() {
  int c = blockIdx.x;
  int b = threadIdx.x;
  float s[NSLOTS];
#pragma unroll
  for (int j = 0; j < NSLOTS; j++) s[j] = (j == b) ? 1.f : 0.f;
  int t0 = c * CLEN;
  for (int t = t0; t < t0 + CLEN; t++) {
    gate_step(s, key_div4(t));
    s[0] = 0.f;
  }
#pragma unroll
  for (int j = 0; j < NSLOTS; j++) d_amat[(c * NSLOTS + j) * NSLOTS + b] = s[j];
}

// ================= scan pass 1: local scans =================
__global__ __launch_bounds__(128) void scan_pass1() {
  int c = blockIdx.x;
  int g = blockIdx.y * 128 + threadIdx.x;
  const float* src = (g < 512) ? (d_kk + g) : (d_vv + (g - 512));
  float s[NSLOTS];
#pragma unroll
  for (int j = 0; j < NSLOTS; j++) s[j] = 0.f;
  int t0 = c * CLEN;
  for (int t = t0; t < t0 + CLEN; t++) {
    gate_step(s, key_div4(t));
    s[0] = src[(size_t)t * 512];
  }
#pragma unroll
  for (int j = 0; j < NSLOTS; j++) d_lend[(c * NDIMS + g) * NSLOTS + j] = s[j];
}

// ================= scan pass 2: carry propagation =================
__global__ __launch_bounds__(256) void scan_pass2() {
  int g = blockIdx.x * 8 + (threadIdx.x >> 5);
  int j = threadIdx.x & 31;
  float carry = 0.f;
  for (int c = 0; c < NCHUNK; c++) {
    d_carryb[(c * NDIMS + g) * NSLOTS + j] = carry;
    float nc = d_lend[(c * NDIMS + g) * NSLOTS + j];
    const float* arow = &d_amat[(c * NSLOTS + j) * NSLOTS];
#pragma unroll
    for (int i = 0; i < NSLOTS; i++) {
      float ci = __shfl_sync(0xffffffffu, carry, i);
      nc = fmaf(arow[i], ci, nc);
    }
    carry = nc;
  }
}

// ================= scan pass 3: seeded re-scan, write full states =================
__global__ __launch_bounds__(128) void scan_pass3() {
  int c = blockIdx.x;
  int g = blockIdx.y * 128 + threadIdx.x;
  const float* src = (g < 512) ? (d_kk + g) : (d_vv + (g - 512));
  float s[NSLOTS];
#pragma unroll
  for (int j = 0; j < NSLOTS; j++) s[j] = d_carryb[(c * NDIMS + g) * NSLOTS + j];
  int t0 = c * CLEN;
  for (int t = t0; t < t0 + CLEN; t++) {
    gate_step(s, key_div4(t));
    s[0] = src[(size_t)t * 512];
    float4* dst = (float4*)&d_state[((size_t)t * NDIMS + g) * NSLOTS];
#pragma unroll
    for (int q = 0; q < 8; q++)
      dst[q] = make_float4(s[q * 4 + 0], s[q * 4 + 1], s[q * 4 + 2], s[q * 4 + 3]);
  }
}

// ================= fused rmsnorm + attention =================
__global__ __launch_bounds__(128) void attn_kernel(
    const float* __restrict__ key_pos, const float* __restrict__ ln_k_w,
    const float* __restrict__ ln_v_w) {
  __shared__ float ksh[NSLOTS][129];
  __shared__ float vsh[NSLOTS][129];
  __shared__ float qsh[4][128];
  __shared__ float rinv_k[NSLOTS];
  __shared__ float rinv_v[NSLOTS];
  __shared__ float psh[4][NSLOTS];

  const int t = blockIdx.x;
  const int kv = blockIdx.y;
  const int tid = threadIdx.x;

  const float* kbase = &d_state[((size_t)t * NDIMS + kv * 128) * NSLOTS];
  const float* vbase = &d_state[((size_t)t * NDIMS + 512 + kv * 128) * NSLOTS];

#pragma unroll
  for (int it = 0; it < 32; it++) {
    int idx = tid + it * 128;
    int d = idx >> 5, j = idx & 31;
    ksh[j][d] = kbase[idx] + key_pos[idx];
    vsh[j][d] = vbase[idx];
  }
#pragma unroll
  for (int it = 0; it < 4; it++) {
    int idx = tid + it * 128;
    qsh[idx >> 7][idx & 127] = d_qq[(size_t)t * 2048 + kv * 512 + idx] * ln_k_w[idx & 127];
  }
  __syncthreads();

  if (tid < 32) {
    float ss = 0.f;
    for (int d = 0; d < 128; d++) { float x = ksh[tid][d]; ss = fmaf(x, x, ss); }
    rinv_k[tid] = rsqrtf(ss * (1.0f / 128.0f) + EPSF);
  } else if (tid < 64) {
    int e = tid - 32;
    float ss = 0.f;
    for (int d = 0; d < 128; d++) { float x = vsh[e][d]; ss = fmaf(x, x, ss); }
    rinv_v[e] = rsqrtf(ss * (1.0f / 128.0f) + EPSF);
  }
  __syncthreads();

  {
    int x = tid >> 5, e = tid & 31;
    float acc = 0.f;
    for (int d = 0; d < 128; d++) acc = fmaf(qsh[x][d], ksh[e][d], acc);
    float l = acc * rinv_k[e];
    float m = l;
#pragma unroll
    for (int off = 16; off; off >>= 1) m = fmaxf(m, __shfl_xor_sync(0xffffffffu, m, off));
    float p = expf(l - m);
    float sum = p;
#pragma unroll
    for (int off = 16; off; off >>= 1) sum += __shfl_xor_sync(0xffffffffu, sum, off);
    psh[x][e] = (p / sum) * rinv_v[e];
  }
  __syncthreads();

  {
    int d = tid;
    float acc[4] = {0.f, 0.f, 0.f, 0.f};
    for (int e = 0; e < NSLOTS; e++) {
      float vv = vsh[e][d];
#pragma unroll
      for (int x = 0; x < 4; x++) acc[x] = fmaf(psh[x][e], vv, acc[x]);
    }
    float w = ln_v_w[d];
#pragma unroll
    for (int x = 0; x < 4; x++)
      d_attn[(size_t)t * 2048 + kv * 512 + x * 128 + d] = acc[x] * w;
  }
}

// ================= launch =================
extern "C" void kernel_launch(void* const* d_in, const int* in_sizes, int n_in,
                              void* d_out, int out_size) {
  const float* q        = (const float*)d_in[0];
  const float* k        = (const float*)d_in[1];
  const float* v        = (const float*)d_in[2];
  const float* wq       = (const float*)d_in[3];
  const float* wk       = (const float*)d_in[4];
  const float* wv       = (const float*)d_in[5];
  const float* wd       = (const float*)d_in[6];
  const float* key_pos  = (const float*)d_in[7];
  const float* query_pos= (const float*)d_in[8];
  const float* ln_k_w   = (const float*)d_in[9];
  const float* ln_v_w   = (const float*)d_in[10];

  float *p_kk, *p_vv, *p_qq, *p_attn;
  cudaGetSymbolAddress((void**)&p_kk, d_kk);
  cudaGetSymbolAddress((void**)&p_vv, d_vv);
  cudaGetSymbolAddress((void**)&p_qq, d_qq);
  cudaGetSymbolAddress((void**)&p_attn, d_attn);

  dim3 blk(256);
  // projections (tensor-core, 3-term bf16 compensation)
  mma_gemm<<<dim3(512 / TBN, LSEQ / TBM), blk>>>(k, wk, p_kk, LSEQ, 512, EMB, INV_SCALE, nullptr);
  mma_gemm<<<dim3(512 / TBN, LSEQ / TBM), blk>>>(v, wv, p_vv, LSEQ, 512, EMB, 1.0f, nullptr);
  mma_gemm<<<dim3(2048 / TBN, LSEQ / TBM), blk>>>(q, wq, p_qq, LSEQ, 2048, EMB, INV_SCALE, query_pos);
  // chunked linear-recurrence scan
  amat_kernel<<<NCHUNK, 32>>>();
  scan_pass1<<<dim3(NCHUNK, 8), 128>>>();
  scan_pass2<<<128, 256>>>();
  scan_pass3<<<dim3(NCHUNK, 8), 128>>>();
  // rmsnorm + slot attention
  attn_kernel<<<dim3(LSEQ, KVHEADS), 128>>>(key_pos, ln_k_w, ln_v_w);
  // output projection
  mma_gemm<<<dim3(2048 / TBN, LSEQ / TBM), blk>>>(p_attn, wd, (float*)d_out, LSEQ, 2048, 2048, 1.0f, nullptr);
}

// round 3
// speedup vs baseline: 1.6915x; 1.6915x over previous
#include <cuda_runtime.h>
#include <cuda_bf16.h>
#include <math.h>

// ================= problem constants =================
#define LSEQ 4096
#define EMB 2048
#define KVHEADS 4
#define NSLOTS 32
#define NDIMS 1024
#define NCHUNK 32
#define CLEN 128
#define RHALF 0.70710678118654752f
#define INV_SCALE 0.29730177875068026f   // 1 / 128^0.25
#define EPSF 1e-6f
#define KP 6144                          // K' = 3 * 2048 (hi|lo|hi concat)
#define NKT (KP / 32)                    // 192 k-steps

// ================= device scratch =================
__device__ float d_kk[LSEQ * 512];
__device__ float d_vv[LSEQ * 512];
__device__ float d_qq[LSEQ * 2048];
__device__ float d_attn[LSEQ * 2048];
__device__ float d_state[(size_t)LSEQ * NDIMS * NSLOTS];
__device__ float d_lend[NCHUNK * NDIMS * NSLOTS];
__device__ float d_carryb[NCHUNK * NDIMS * NSLOTS];
__device__ float d_amat[NCHUNK * NSLOTS * NSLOTS];
__device__ __nv_bfloat16 d_a3[(size_t)LSEQ * KP];      // activation split [M][3K]
__device__ __nv_bfloat16 d_w3[(size_t)2048 * KP];      // weight split, n-major [N][3K]

// ================= gate recurrence =================
template <int KEY>
__device__ __forceinline__ void merge_shift(float (&s)[NSLOTS]) {
  s[KEY] = RHALF * (s[KEY] + s[KEY - 1]);
#pragma unroll
  for (int j = KEY - 1; j >= 1; --j) s[j] = s[j - 1];
}

__device__ __forceinline__ void gate_step(float (&s)[NSLOTS], int kdiv) {
  switch (kdiv) {
    case 1: merge_shift<4>(s); break;
    case 2: merge_shift<8>(s); break;
    case 3: merge_shift<12>(s); break;
    case 4: merge_shift<16>(s); break;
    case 5: merge_shift<20>(s); break;
    case 6: merge_shift<24>(s); break;
    case 7: merge_shift<28>(s); break;
    default:
#pragma unroll
      for (int j = 31; j >= 1; --j) s[j] = s[j - 1];
      break;
  }
}

__device__ __forceinline__ int key_div4(int t) { return __ffs(~(t & 1023)); }

// ================= split helpers =================
__device__ __forceinline__ void split_bf16(float x, __nv_bfloat16& h, __nv_bfloat16& l) {
  h = __float2bfloat16_rn(x);
  l = __float2bfloat16_rn(x - __bfloat162float(h));
}

// activation split: src [M][2048] fp32 -> dst [M][6144] bf16 as [hi|lo|hi]
__global__ __launch_bounds__(256) void split_act(const float* __restrict__ src,
                                                 __nv_bfloat16* __restrict__ dst) {
  const int K = EMB;
  int idx = blockIdx.x * 256 + threadIdx.x;          // over M*K/4
  float4 v = ((const float4*)src)[idx];
  int c = (idx % (K / 4)) * 4;
  int r = idx / (K / 4);
  __nv_bfloat16 h0, l0, h1, l1, h2, l2, h3, l3;
  split_bf16(v.x, h0, l0); split_bf16(v.y, h1, l1);
  split_bf16(v.z, h2, l2); split_bf16(v.w, h3, l3);
  __nv_bfloat162 hA(h0, h1), hB(h2, h3), lA(l0, l1), lB(l2, l3);
  __nv_bfloat16* base = dst + (size_t)r * KP + c;
  *(__nv_bfloat162*)(base) = hA;            *(__nv_bfloat162*)(base + 2) = hB;
  *(__nv_bfloat162*)(base + K) = lA;        *(__nv_bfloat162*)(base + K + 2) = lB;
  *(__nv_bfloat162*)(base + 2 * K) = hA;    *(__nv_bfloat162*)(base + 2 * K + 2) = hB;
}

// weight split + transpose: src [K=2048][N] fp32 -> dst [N][6144] bf16 as [hi|hi|lo]
__global__ __launch_bounds__(256) void split_wt(const float* __restrict__ src,
                                                __nv_bfloat16* __restrict__ dst, int N) {
  const int K = EMB;
  __shared__ float tile[32][33];
  int n0 = blockIdx.x * 32, k0 = blockIdx.y * 32;
  int tx = threadIdx.x & 31, ty = threadIdx.x >> 5;   // 32x8
#pragma unroll
  for (int i = 0; i < 4; i++)
    tile[ty + 8 * i][tx] = src[(size_t)(k0 + ty + 8 * i) * N + n0 + tx];
  __syncthreads();
#pragma unroll
  for (int i = 0; i < 4; i++) {
    int n = n0 + ty + 8 * i;
    int kk = k0 + tx;
    float x = tile[tx][ty + 8 * i];
    __nv_bfloat16 h, l;
    split_bf16(x, h, l);
    __nv_bfloat16* base = dst + (size_t)n * KP;
    base[kk] = h; base[K + kk] = h; base[2 * K + kk] = l;
  }
}

// ================= bf16 tensor-core GEMM =================
// C[M,N] = alpha * A'[M,KP] @ B'[N,KP]^T (+ bias[col&127])
// 128x128 CTA tile, 256 threads (8 warps 2Mx4N), cp.async double buffer, ldmatrix.
#define SPITCH 40   // bf16 per smem row (conflict-free for stores & ldmatrix)
#define STAGEB (128 * SPITCH * 2)  // bytes per stage per operand

__device__ __forceinline__ void mma16816(float (&c)[4], const unsigned (&a)[4],
                                         unsigned b0, unsigned b1) {
  asm volatile(
      "mma.sync.aligned.m16n8k16.row.col.f32.bf16.bf16.f32 "
      "{%0,%1,%2,%3}, {%4,%5,%6,%7}, {%8,%9}, {%0,%1,%2,%3};"
      : "+f"(c[0]), "+f"(c[1]), "+f"(c[2]), "+f"(c[3])
      : "r"(a[0]), "r"(a[1]), "r"(a[2]), "r"(a[3]), "r"(b0), "r"(b1));
}

#define CP16(dst, src) \
  asm volatile("cp.async.cg.shared.global [%0], [%1], 16;" :: "r"(dst), "l"(src))

__global__ __launch_bounds__(256) void bf16_gemm(
    const __nv_bfloat16* __restrict__ A, const __nv_bfloat16* __restrict__ Bn,
    float* __restrict__ C, int N, float alpha, const float* __restrict__ bias) {
  __shared__ __nv_bfloat16 As[2][128][SPITCH];
  __shared__ __nv_bfloat16 Bs[2][128][SPITCH];

  const int tid = threadIdx.x;
  const int lane = tid & 31, warp = tid >> 5;
  const int wm = (warp & 1) * 64, wn = (warp >> 1) * 32;
  const int g = lane >> 2, t = lane & 3;
  const int crow = blockIdx.y * 128, ccol = blockIdx.x * 128;

  const unsigned sA = (unsigned)__cvta_generic_to_shared(&As[0][0][0]);
  const unsigned sB = (unsigned)__cvta_generic_to_shared(&Bs[0][0][0]);

  // cp.async tiling: 64 rows x 4 chunks(16B) per pass, 2 passes per operand
  const int lr = tid >> 2;
  const int lc = (tid & 3) * 8;
  const __nv_bfloat16* gA = A + (size_t)(crow + lr) * KP + lc;
  const __nv_bfloat16* gB = Bn + (size_t)(ccol + lr) * KP + lc;
  const unsigned dA0 = sA + (lr * SPITCH + lc) * 2;
  const unsigned dA1 = sA + ((lr + 64) * SPITCH + lc) * 2;
  const unsigned dB0 = sB + (lr * SPITCH + lc) * 2;
  const unsigned dB1 = sB + ((lr + 64) * SPITCH + lc) * 2;

  float acc[4][4][4];
#pragma unroll
  for (int i = 0; i < 4; i++)
#pragma unroll
    for (int j = 0; j < 4; j++)
#pragma unroll
      for (int r = 0; r < 4; r++) acc[i][j][r] = 0.f;

  // precomputed ldmatrix lane addresses (byte offsets within a stage)
  const int a_row = wm + (lane & 15);
  const int a_kof = (lane >> 4) << 3;
  const int b_row = wn + ((lane >> 4) << 3) + (lane & 7);
  const int b_kof = ((lane >> 3) & 1) << 3;

  // prologue: stage 0
  {
    const __nv_bfloat16* pa = gA;
    const __nv_bfloat16* pb = gB;
    CP16(dA0, pa); CP16(dA1, pa + (size_t)64 * KP);
    CP16(dB0, pb); CP16(dB1, pb + (size_t)64 * KP);
    asm volatile("cp.async.commit_group;");
  }

  for (int kt = 0; kt < NKT; kt++) {
    const int st = kt & 1;
    if (kt + 1 < NKT) {
      const __nv_bfloat16* pa = gA + (size_t)(kt + 1) * 32;
      const __nv_bfloat16* pb = gB + (size_t)(kt + 1) * 32;
      const unsigned so = (st ^ 1) * STAGEB;
      CP16(dA0 + so, pa); CP16(dA1 + so, pa + (size_t)64 * KP);
      CP16(dB0 + so, pb); CP16(dB1 + so, pb + (size_t)64 * KP);
      asm volatile("cp.async.commit_group;");
      asm volatile("cp.async.wait_group 1;");
    } else {
      asm volatile("cp.async.wait_group 0;");
    }
    __syncthreads();

    const unsigned so = st * STAGEB;
#pragma unroll
    for (int ks = 0; ks < 2; ks++) {
      const int k0 = ks * 16;
      unsigned a[4][4];
#pragma unroll
      for (int i = 0; i < 4; i++) {
        unsigned addr = sA + so + (((a_row + i * 16) * SPITCH) + k0 + a_kof) * 2;
        asm volatile(
            "ldmatrix.sync.aligned.m8n8.x4.shared.b16 {%0,%1,%2,%3}, [%4];"
            : "=r"(a[i][0]), "=r"(a[i][1]), "=r"(a[i][2]), "=r"(a[i][3])
            : "r"(addr));
      }
      unsigned b[4][2];
#pragma unroll
      for (int jj = 0; jj < 2; jj++) {
        unsigned addr = sB + so + (((b_row + jj * 16) * SPITCH) + k0 + b_kof) * 2;
        asm volatile(
            "ldmatrix.sync.aligned.m8n8.x4.shared.b16 {%0,%1,%2,%3}, [%4];"
            : "=r"(b[2 * jj][0]), "=r"(b[2 * jj][1]),
              "=r"(b[2 * jj + 1][0]), "=r"(b[2 * jj + 1][1])
            : "r"(addr));
      }
#pragma unroll
      for (int i = 0; i < 4; i++)
#pragma unroll
        for (int j = 0; j < 4; j++) mma16816(acc[i][j], a[i], b[j][0], b[j][1]);
    }
    __syncthreads();
  }

  // epilogue
#pragma unroll
  for (int i = 0; i < 4; i++) {
#pragma unroll
    for (int j = 0; j < 4; j++) {
      int row = crow + wm + i * 16 + g;
      int col = ccol + wn + j * 8 + 2 * t;
      float b0 = bias ? bias[col & 127] : 0.f;
      float b1 = bias ? bias[(col + 1) & 127] : 0.f;
      float2 v0 = make_float2(alpha * acc[i][j][0] + b0, alpha * acc[i][j][1] + b1);
      float2 v1 = make_float2(alpha * acc[i][j][2] + b0, alpha * acc[i][j][3] + b1);
      *(float2*)(C + (size_t)row * N + col) = v0;
      *(float2*)(C + (size_t)(row + 8) * N + col) = v1;
    }
  }
}

// ================= scan pass A: composed chunk maps =================
__global__ void amat_kernel() {
  int c = blockIdx.x;
  int b = threadIdx.x;
  float s[NSLOTS];
#pragma unroll
  for (int j = 0; j < NSLOTS; j++) s[j] = (j == b) ? 1.f : 0.f;
  int t0 = c * CLEN;
  for (int t = t0; t < t0 + CLEN; t++) {
    gate_step(s, key_div4(t));
    s[0] = 0.f;
  }
#pragma unroll
  for (int j = 0; j < NSLOTS; j++) d_amat[(c * NSLOTS + j) * NSLOTS + b] = s[j];
}

// ================= scan pass 1: local scans =================
__global__ __launch_bounds__(128) void scan_pass1() {
  int c = blockIdx.x;
  int g = blockIdx.y * 128 + threadIdx.x;
  const float* src = (g < 512) ? (d_kk + g) : (d_vv + (g - 512));
  float s[NSLOTS];
#pragma unroll
  for (int j = 0; j < NSLOTS; j++) s[j] = 0.f;
  int t0 = c * CLEN;
  for (int t = t0; t < t0 + CLEN; t++) {
    gate_step(s, key_div4(t));
    s[0] = src[(size_t)t * 512];
  }
#pragma unroll
  for (int j = 0; j < NSLOTS; j++) d_lend[(c * NDIMS + g) * NSLOTS + j] = s[j];
}

// ================= scan pass 2: carry propagation =================
__global__ __launch_bounds__(256) void scan_pass2() {
  int g = blockIdx.x * 8 + (threadIdx.x >> 5);
  int j = threadIdx.x & 31;
  float carry = 0.f;
  for (int c = 0; c < NCHUNK; c++) {
    d_carryb[(c * NDIMS + g) * NSLOTS + j] = carry;
    float nc = d_lend[(c * NDIMS + g) * NSLOTS + j];
    const float* arow = &d_amat[(c * NSLOTS + j) * NSLOTS];
#pragma unroll
    for (int i = 0; i < NSLOTS; i++) {
      float ci = __shfl_sync(0xffffffffu, carry, i);
      nc = fmaf(arow[i], ci, nc);
    }
    carry = nc;
  }
}

// ================= scan pass 3: seeded re-scan =================
__global__ __launch_bounds__(128) void scan_pass3() {
  int c = blockIdx.x;
  int g = blockIdx.y * 128 + threadIdx.x;
  const float* src = (g < 512) ? (d_kk + g) : (d_vv + (g - 512));
  float s[NSLOTS];
#pragma unroll
  for (int j = 0; j < NSLOTS; j++) s[j] = d_carryb[(c * NDIMS + g) * NSLOTS + j];
  int t0 = c * CLEN;
  for (int t = t0; t < t0 + CLEN; t++) {
    gate_step(s, key_div4(t));
    s[0] = src[(size_t)t * 512];
    float4* dst = (float4*)&d_state[((size_t)t * NDIMS + g) * NSLOTS];
#pragma unroll
    for (int q = 0; q < 8; q++)
      dst[q] = make_float4(s[q * 4 + 0], s[q * 4 + 1], s[q * 4 + 2], s[q * 4 + 3]);
  }
}

// ================= fused rmsnorm + attention =================
__global__ __launch_bounds__(128) void attn_kernel(
    const float* __restrict__ key_pos, const float* __restrict__ ln_k_w,
    const float* __restrict__ ln_v_w) {
  __shared__ float ksh[NSLOTS][129];
  __shared__ float vsh[NSLOTS][129];
  __shared__ float qsh[4][128];
  __shared__ float rinv_k[NSLOTS];
  __shared__ float rinv_v[NSLOTS];
  __shared__ float psh[4][NSLOTS];

  const int t = blockIdx.x;
  const int kv = blockIdx.y;
  const int tid = threadIdx.x;

  const float* kbase = &d_state[((size_t)t * NDIMS + kv * 128) * NSLOTS];
  const float* vbase = &d_state[((size_t)t * NDIMS + 512 + kv * 128) * NSLOTS];

#pragma unroll
  for (int it = 0; it < 32; it++) {
    int idx = tid + it * 128;
    int d = idx >> 5, j = idx & 31;
    ksh[j][d] = kbase[idx] + key_pos[idx];
    vsh[j][d] = vbase[idx];
  }
#pragma unroll
  for (int it = 0; it < 4; it++) {
    int idx = tid + it * 128;
    qsh[idx >> 7][idx & 127] = d_qq[(size_t)t * 2048 + kv * 512 + idx] * ln_k_w[idx & 127];
  }
  __syncthreads();

  if (tid < 32) {
    float ss = 0.f;
    for (int d = 0; d < 128; d++) { float x = ksh[tid][d]; ss = fmaf(x, x, ss); }
    rinv_k[tid] = rsqrtf(ss * (1.0f / 128.0f) + EPSF);
  } else if (tid < 64) {
    int e = tid - 32;
    float ss = 0.f;
    for (int d = 0; d < 128; d++) { float x = vsh[e][d]; ss = fmaf(x, x, ss); }
    rinv_v[e] = rsqrtf(ss * (1.0f / 128.0f) + EPSF);
  }
  __syncthreads();

  {
    int x = tid >> 5, e = tid & 31;
    float acc = 0.f;
    for (int d = 0; d < 128; d++) acc = fmaf(qsh[x][d], ksh[e][d], acc);
    float l = acc * rinv_k[e];
    float m = l;
#pragma unroll
    for (int off = 16; off; off >>= 1) m = fmaxf(m, __shfl_xor_sync(0xffffffffu, m, off));
    float p = expf(l - m);
    float sum = p;
#pragma unroll
    for (int off = 16; off; off >>= 1) sum += __shfl_xor_sync(0xffffffffu, sum, off);
    psh[x][e] = (p / sum) * rinv_v[e];
  }
  __syncthreads();

  {
    int d = tid;
    float acc[4] = {0.f, 0.f, 0.f, 0.f};
    for (int e = 0; e < NSLOTS; e++) {
      float vv = vsh[e][d];
#pragma unroll
      for (int x = 0; x < 4; x++) acc[x] = fmaf(psh[x][e], vv, acc[x]);
    }
    float w = ln_v_w[d];
#pragma unroll
    for (int x = 0; x < 4; x++)
      d_attn[(size_t)t * 2048 + kv * 512 + x * 128 + d] = acc[x] * w;
  }
}

// ================= launch =================
extern "C" void kernel_launch(void* const* d_in, const int* in_sizes, int n_in,
                              void* d_out, int out_size) {
  const float* q        = (const float*)d_in[0];
  const float* k        = (const float*)d_in[1];
  const float* v        = (const float*)d_in[2];
  const float* wq       = (const float*)d_in[3];
  const float* wk       = (const float*)d_in[4];
  const float* wv       = (const float*)d_in[5];
  const float* wd       = (const float*)d_in[6];
  const float* key_pos  = (const float*)d_in[7];
  const float* query_pos= (const float*)d_in[8];
  const float* ln_k_w   = (const float*)d_in[9];
  const float* ln_v_w   = (const float*)d_in[10];

  float *p_kk, *p_vv, *p_qq, *p_attn;
  __nv_bfloat16 *p_a3, *p_w3;
  cudaGetSymbolAddress((void**)&p_kk, d_kk);
  cudaGetSymbolAddress((void**)&p_vv, d_vv);
  cudaGetSymbolAddress((void**)&p_qq, d_qq);
  cudaGetSymbolAddress((void**)&p_attn, d_attn);
  cudaGetSymbolAddress((void**)&p_a3, d_a3);
  cudaGetSymbolAddress((void**)&p_w3, d_w3);

  const int actBlocks = LSEQ * EMB / 4 / 256;   // 8192

  // ---- k projection ----
  split_act<<<actBlocks, 256>>>(k, p_a3);
  split_wt<<<dim3(512 / 32, EMB / 32), 256>>>(wk, p_w3, 512);
  bf16_gemm<<<dim3(512 / 128, LSEQ / 128), 256>>>(p_a3, p_w3, p_kk, 512, INV_SCALE, nullptr);
  // ---- v projection ----
  split_act<<<actBlocks, 256>>>(v, p_a3);
  split_wt<<<dim3(512 / 32, EMB / 32), 256>>>(wv, p_w3, 512);
  bf16_gemm<<<dim3(512 / 128, LSEQ / 128), 256>>>(p_a3, p_w3, p_vv, 512, 1.0f, nullptr);
  // ---- q projection (bias = query_pos per 128) ----
  split_act<<<actBlocks, 256>>>(q, p_a3);
  split_wt<<<dim3(2048 / 32, EMB / 32), 256>>>(wq, p_w3, 2048);
  bf16_gemm<<<dim3(2048 / 128, LSEQ / 128), 256>>>(p_a3, p_w3, p_qq, 2048, INV_SCALE, query_pos);
  // ---- chunked linear-recurrence scan ----
  amat_kernel<<<NCHUNK, 32>>>();
  scan_pass1<<<dim3(NCHUNK, 8), 128>>>();
  scan_pass2<<<128, 256>>>();
  scan_pass3<<<dim3(NCHUNK, 8), 128>>>();
  // ---- rmsnorm + slot attention ----
  attn_kernel<<<dim3(LSEQ, KVHEADS), 128>>>(key_pos, ln_k_w, ln_v_w);
  // ---- output projection ----
  split_act<<<actBlocks, 256>>>(p_attn, p_a3);
  split_wt<<<dim3(2048 / 32, EMB / 32), 256>>>(wd, p_w3, 2048);
  bf16_gemm<<<dim3(2048 / 128, LSEQ / 128), 256>>>(p_a3, p_w3, (float*)d_out, 2048, 1.0f, nullptr);
}